// round 13
// baseline (speedup 1.0000x reference)
#include <cuda_runtime.h>
#include <cstdint>

// ============================================================================
// Persistent 2-layer LSTM for GB300 (sm_103a) — R8.
//   R6 topology (148 CTAs, per-CTA smem weights, lane=batch, split-counter
//   sync) at 1024 threads/CTA: 32 warps = 8/SMSP for latency hiding.
//   Per-warp k-slices halved; register budget trimmed to fit 64 regs/thread.
// ============================================================================

#define NCTA 148
#define SMEM_W0   0                 // [768][8] float2  = 49152 B
#define SMEM_W1   49152             // [1024][8] float2 = 65536 B
#define SMEM_RED  114688            // 32 warps x 8 pairs x 32 lanes x 8B = 65536 B
#define SMEM_TOTAL 180224           // 176 KB

// ------------------------- device-global scratch ---------------------------
__device__ float g_xT[1024 * 256 * 32];            // x transposed: [t][c][b]
__device__ float g_h[2][2][512][32];               // [layer][parity][unit][batch]
__device__ float2 g_w0[(size_t)NCTA * 768 * 8];    // per-CTA weight images, layer0
__device__ float2 g_w1[(size_t)NCTA * 1024 * 8];   // per-CTA weight images, layer1
__device__ unsigned g_cnt[2];                      // split barrier counters

// ------------------------------ helpers ------------------------------------
static __device__ __forceinline__ void cp16(void* d, const void* s) {
    unsigned ds = (unsigned)__cvta_generic_to_shared(d);
    asm volatile("cp.async.cg.shared.global [%0], [%1], 16;" :: "r"(ds), "l"(s));
}
static __device__ __forceinline__ float sigm(float x) {
    return 1.0f / (1.0f + __expf(-x));
}
static __device__ __forceinline__ float tanh_f(float x) {
    return 1.0f - 2.0f / (__expf(2.0f * x) + 1.0f);
}
static __device__ __forceinline__ unsigned long long pkdup(float v) {
    unsigned u = __float_as_uint(v);
    unsigned long long r;
    asm("mov.b64 %0, {%1, %1};" : "=l"(r) : "r"(u));
    return r;
}
static __device__ __forceinline__ void ffma2(unsigned long long& acc,
                                             unsigned long long a,
                                             unsigned long long b) {
    asm("fma.rn.f32x2 %0, %1, %2, %0;" : "+l"(acc) : "l"(a), "l"(b));
}
static __device__ __forceinline__ float ldcg(const float* p) {
    float v;
    asm volatile("ld.global.cg.f32 %0, [%1];" : "=f"(v) : "l"(p));
    return v;
}

// spin until *cp >= tgt (tid0 spins, CTA released together)
static __device__ __forceinline__ void wait_cnt(unsigned* cp, unsigned tgt) {
    if (threadIdx.x == 0) {
        unsigned v;
        do {
            asm volatile("ld.acquire.gpu.global.u32 %0, [%1];" : "=r"(v) : "l"(cp) : "memory");
        } while ((int)(v - tgt) < 0);
    }
    __syncthreads();
}
// publish: red.release orders all prior global writes at gpu scope
static __device__ __forceinline__ void arrive_cnt(unsigned* cp) {
    __syncthreads();
    if (threadIdx.x == 0)
        asm volatile("red.release.gpu.global.add.u32 [%0], 1;" :: "l"(cp) : "memory");
}

// acc[p] += sum_{kk<LEN} h[kk][lane] * w[(ko+kk)][p], h streamed from L2 (.cg)
template <int LEN>
static __device__ __forceinline__ void mm_ldg(
    const ulonglong2* __restrict__ wv, int ko, const float* __restrict__ src,
    unsigned long long acc[8])
{
    float hv[4];
    #pragma unroll
    for (int i = 0; i < 4; i++) hv[i] = ldcg(src + i * 32);
    const ulonglong2* wp = wv + (size_t)ko * 4;
    #pragma unroll 2
    for (int kk = 0; kk < LEN; kk++) {
        float h = hv[kk & 3];
        if (kk + 4 < LEN) hv[kk & 3] = ldcg(src + (kk + 4) * 32);
        unsigned long long h2 = pkdup(h);
        ulonglong2 wa = wp[kk * 4 + 0];
        ulonglong2 wb = wp[kk * 4 + 1];
        ffma2(acc[0], h2, wa.x);
        ffma2(acc[1], h2, wa.y);
        ffma2(acc[2], h2, wb.x);
        ffma2(acc[3], h2, wb.y);
        ulonglong2 wc = wp[kk * 4 + 2];
        ulonglong2 wd = wp[kk * 4 + 3];
        ffma2(acc[4], h2, wc.x);
        ffma2(acc[5], h2, wc.y);
        ffma2(acc[6], h2, wd.x);
        ffma2(acc[7], h2, wd.y);
    }
}

// --------------------------- persistent kernel -----------------------------
__global__ void __launch_bounds__(1024, 1)
lstm_persist(const float* __restrict__ b0f, const float* __restrict__ b0i,
             const float* __restrict__ b0c, const float* __restrict__ b0o,
             const float* __restrict__ b1f, const float* __restrict__ b1i,
             const float* __restrict__ b1c, const float* __restrict__ b1o,
             float* __restrict__ out)
{
    extern __shared__ char smem[];
    const ulonglong2* w0 = (const ulonglong2*)(smem + SMEM_W0);
    const ulonglong2* w1 = (const ulonglong2*)(smem + SMEM_W1);
    float2*      red = (float2*)(smem + SMEM_RED);
    unsigned long long* redu = (unsigned long long*)red;

    const int tid  = threadIdx.x;
    const int lane = tid & 31;       // = batch index
    const int warp = tid >> 5;       // 0..31
    const int cta  = blockIdx.x;
    const int U     = (cta < 68) ? 4 : 3;                       // 68*4+80*3=512
    const int ubase = (cta < 68) ? 4 * cta : 272 + 3 * (cta - 68);

    // load this CTA's weight images into SMEM (once): 114688 B, 16 KB/iter
    {
        const char* s0 = (const char*)(g_w0 + (size_t)cta * 768 * 8);
        #pragma unroll
        for (int i = 0; i < 3; i++)
            cp16((char*)smem + SMEM_W0 + tid * 16 + i * 16384, s0 + tid * 16 + i * 16384);
        const char* s1 = (const char*)(g_w1 + (size_t)cta * 1024 * 8);
        #pragma unroll
        for (int i = 0; i < 4; i++)
            cp16((char*)smem + SMEM_W1 + tid * 16 + i * 16384, s1 + tid * 16 + i * 16384);
        asm volatile("cp.async.commit_group;" ::: "memory");
        asm volatile("cp.async.wait_group 0;" ::: "memory");
    }
    __syncthreads();

    // warps 0-3 finalize L0 unit j; warps 4-7 finalize L1 unit j; 8-31 compute only
    const int j  = warp & 3;
    const int uu = ubase + (j < U ? j : 0);
    float Bf = 0.f, Bi = 0.f, Bc = 0.f, Bo = 0.f;
    if (warp < 4)        { Bf = b0f[uu]; Bi = b0i[uu]; Bc = b0c[uu]; Bo = b0o[uu]; }
    else if (warp < 8)   { Bf = b1f[uu]; Bi = b1i[uu]; Bc = b1c[uu]; Bo = b1o[uu]; }
    float cst = 0.0f;                       // cell state lives in a register
    unsigned tgt = 0;                       // = t * NCTA at loop top
    unsigned long long acc[8];

    for (int t = 0; t < 1024; t++) {
        const int par = t & 1, par2 = par ^ 1;

        // ================= L0(t): gates0 = W0 . [x(t); h0(t-1)] ============
        #pragma unroll
        for (int p = 0; p < 8; p++) acc[p] = 0ULL;
        // x part: k in [warp*8, warp*8+8), no cross-CTA dependence
        mm_ldg<8>(w0, warp * 8,
                  g_xT + (size_t)t * 8192 + (warp * 8) * 32 + lane, acc);
        // h0(t-1): published with cnt0 == t*NCTA
        wait_cnt(&g_cnt[0], tgt);
        mm_ldg<16>(w0, 256 + warp * 16,
                   &g_h[0][par2][warp * 16][0] + lane, acc);

        #pragma unroll
        for (int p = 0; p < 8; p++) redu[(warp * 8 + p) * 32 + lane] = acc[p];
        __syncthreads();
        if (warp < 4) {
            float2 sfi = make_float2(0.f, 0.f), sco = make_float2(0.f, 0.f);
            #pragma unroll
            for (int w = 0; w < 32; w++) {
                float2 a = red[(w * 8 + 2 * j) * 32 + lane];
                float2 b = red[(w * 8 + 2 * j + 1) * 32 + lane];
                sfi.x += a.x; sfi.y += a.y; sco.x += b.x; sco.y += b.y;
            }
            float f  = sigm(sfi.x + Bf);
            float ig = sigm(sfi.y + Bi);
            float gg = tanh_f(sco.x + Bc);
            float o  = sigm(sco.y + Bo);
            cst = f * cst + ig * gg;
            float h = o * tanh_f(cst);
            if (j < U) g_h[0][par][ubase + j][lane] = h;
        }
        arrive_cnt(&g_cnt[0]);   // cnt0 -> (t+1)*NCTA

        // ================= L1(t): gates1 = W1 . [h0(t); h1(t-1)] ===========
        #pragma unroll
        for (int p = 0; p < 8; p++) acc[p] = 0ULL;
        // h1(t-1): published with cnt1 == t*NCTA (slack: all of L0(t))
        wait_cnt(&g_cnt[1], tgt);
        mm_ldg<16>(w1, 512 + warp * 16,
                   &g_h[1][par2][warp * 16][0] + lane, acc);
        // h0(t): published just above; slack = h1-old half
        wait_cnt(&g_cnt[0], tgt + NCTA);
        mm_ldg<16>(w1, warp * 16,
                   &g_h[0][par][warp * 16][0] + lane, acc);

        #pragma unroll
        for (int p = 0; p < 8; p++) redu[(warp * 8 + p) * 32 + lane] = acc[p];
        __syncthreads();
        if (warp >= 4 && warp < 8) {
            float2 sfi = make_float2(0.f, 0.f), sco = make_float2(0.f, 0.f);
            #pragma unroll
            for (int w = 0; w < 32; w++) {
                float2 a = red[(w * 8 + 2 * j) * 32 + lane];
                float2 b = red[(w * 8 + 2 * j + 1) * 32 + lane];
                sfi.x += a.x; sfi.y += a.y; sco.x += b.x; sco.y += b.y;
            }
            float f  = sigm(sfi.x + Bf);
            float ig = sigm(sfi.y + Bi);
            float gg = tanh_f(sco.x + Bc);
            float o  = sigm(sco.y + Bo);
            cst = f * cst + ig * gg;
            float h = o * tanh_f(cst);
            if (j < U) {
                int u = ubase + j;
                g_h[1][par][u][lane] = h;
                out[(size_t)lane * 524288 + (size_t)t * 512 + u] = h;
            }
        }
        arrive_cnt(&g_cnt[1]);   // cnt1 -> (t+1)*NCTA

        tgt += NCTA;
    }
}

// ------------------------------ fused prep ---------------------------------
// segments: [0, 8388608) transpose x | [.., +65536) zero g_h (+counters)
//           [.., +909312) w0 image   | [.., +1212416) w1 image
__global__ void prep_all(const float* __restrict__ x,
                         const float* __restrict__ W0f, const float* __restrict__ W0i,
                         const float* __restrict__ W0c, const float* __restrict__ W0o,
                         const float* __restrict__ W1f, const float* __restrict__ W1i,
                         const float* __restrict__ W1c, const float* __restrict__ W1o)
{
    long idx = (long)blockIdx.x * blockDim.x + threadIdx.x;
    if (idx < 8388608L) {                                   // x transpose
        int b = (int)(idx & 31);
        int c = (int)((idx >> 5) & 255);
        int t = (int)(idx >> 13);
        g_xT[idx] = x[(size_t)b * 262144 + (size_t)t * 256 + c];
        return;
    }
    idx -= 8388608L;
    if (idx < 65536L) {                                     // zero h state + counters
        if (idx < 2) g_cnt[idx] = 0u;
        (&g_h[0][0][0][0])[idx] = 0.f;
        return;
    }
    idx -= 65536L;
    int layer; long widx; int K;
    const float *Wf, *Wi, *Wc, *Wo;
    if (idx < (long)NCTA * 768 * 8) {
        layer = 0; widx = idx; K = 768; Wf = W0f; Wi = W0i; Wc = W0c; Wo = W0o;
    } else {
        layer = 1; widx = idx - (long)NCTA * 768 * 8; K = 1024;
        Wf = W1f; Wi = W1i; Wc = W1c; Wo = W1o;
        if (widx >= (long)NCTA * 1024 * 8) return;
    }
    int  p   = (int)(widx & 7);
    long r   = widx >> 3;
    int  k   = (int)(r % K);
    int  cta = (int)(r / K);
    int  Uc    = (cta < 68) ? 4 : 3;
    int  ubase = (cta < 68) ? 4 * cta : 272 + 3 * (cta - 68);
    int  jj = p >> 1, q = p & 1;
    float2 v = make_float2(0.f, 0.f);
    if (jj < Uc) {
        size_t o = (size_t)(ubase + jj) * K + k;
        v = q ? make_float2(Wc[o], Wo[o]) : make_float2(Wf[o], Wi[o]);
    }
    if (layer) g_w1[widx] = v; else g_w0[widx] = v;
}

// ------------------------------- launcher ----------------------------------
extern "C" void kernel_launch(void* const* d_in, const int* in_sizes, int n_in,
                              void* d_out, int out_size)
{
    const float* x   = (const float*)d_in[0];
    const float* W0f = (const float*)d_in[1];
    const float* b0f = (const float*)d_in[2];
    const float* W0i = (const float*)d_in[3];
    const float* b0i = (const float*)d_in[4];
    const float* W0c = (const float*)d_in[5];
    const float* b0c = (const float*)d_in[6];
    const float* W0o = (const float*)d_in[7];
    const float* b0o = (const float*)d_in[8];
    const float* W1f = (const float*)d_in[9];
    const float* b1f = (const float*)d_in[10];
    const float* W1i = (const float*)d_in[11];
    const float* b1i = (const float*)d_in[12];
    const float* W1c = (const float*)d_in[13];
    const float* b1c = (const float*)d_in[14];
    const float* W1o = (const float*)d_in[15];
    const float* b1o = (const float*)d_in[16];
    float* out = (float*)d_out;

    cudaFuncSetAttribute(lstm_persist,
                         cudaFuncAttributeMaxDynamicSharedMemorySize, SMEM_TOTAL);

    // total prep items = 8388608 + 65536 + 909312 + 1212416 = 10575872 = 41312*256
    prep_all<<<41312, 256>>>(x, W0f, W0i, W0c, W0o, W1f, W1i, W1c, W1o);
    lstm_persist<<<NCTA, 1024, SMEM_TOTAL>>>(b0f, b0i, b0c, b0o,
                                             b1f, b1i, b1c, b1o, out);
}

// round 14
// speedup vs baseline: 1.4101x; 1.4101x over previous
#include <cuda_runtime.h>
#include <cstdint>

// ============================================================================
// Persistent 2-layer LSTM for GB300 (sm_103a) — R9.
//   R6 topology: 148 CTAs x 512 thr (16 warps), per-CTA smem weight images,
//   lane = batch, split-counter grid sync.
//   NEW: fully-unrolled inner loops with explicit register pipelines —
//   weights 3 k-iters deep (LDS lat 29cy covered), h 16 deep (L2 lat covered),
//   no per-iteration guards (they caused R8's ALU blowup).
// ============================================================================

#define NCTA 148
#define SMEM_W0   0                 // [768][8] float2  = 49152 B
#define SMEM_W1   49152             // [1024][8] float2 = 65536 B
#define SMEM_RED  114688            // 16 warps x 8 pairs x 32 lanes x 8B = 32768 B
#define SMEM_TOTAL 147456           // 144 KB

// ------------------------- device-global scratch ---------------------------
__device__ float g_xT[1024 * 256 * 32];            // x transposed: [t][c][b]
__device__ float g_h[2][2][512][32];               // [layer][parity][unit][batch]
__device__ float2 g_w0[(size_t)NCTA * 768 * 8];    // per-CTA weight images, layer0
__device__ float2 g_w1[(size_t)NCTA * 1024 * 8];   // per-CTA weight images, layer1
__device__ unsigned g_cnt[2];                      // split barrier counters

// ------------------------------ helpers ------------------------------------
static __device__ __forceinline__ void cp16(void* d, const void* s) {
    unsigned ds = (unsigned)__cvta_generic_to_shared(d);
    asm volatile("cp.async.cg.shared.global [%0], [%1], 16;" :: "r"(ds), "l"(s));
}
static __device__ __forceinline__ float sigm(float x) {
    return 1.0f / (1.0f + __expf(-x));
}
static __device__ __forceinline__ float tanh_f(float x) {
    return 1.0f - 2.0f / (__expf(2.0f * x) + 1.0f);
}
static __device__ __forceinline__ unsigned long long pkdup(float v) {
    unsigned u = __float_as_uint(v);
    unsigned long long r;
    asm("mov.b64 %0, {%1, %1};" : "=l"(r) : "r"(u));
    return r;
}
static __device__ __forceinline__ void ffma2(unsigned long long& acc,
                                             unsigned long long a,
                                             unsigned long long b) {
    asm("fma.rn.f32x2 %0, %1, %2, %0;" : "+l"(acc) : "l"(a), "l"(b));
}
static __device__ __forceinline__ float ldcg(const float* p) {
    float v;
    asm volatile("ld.global.cg.f32 %0, [%1];" : "=f"(v) : "l"(p));
    return v;
}

// spin until *cp >= tgt (tid0 spins, CTA released together)
static __device__ __forceinline__ void wait_cnt(unsigned* cp, unsigned tgt) {
    if (threadIdx.x == 0) {
        unsigned v;
        for (;;) {
            asm volatile("ld.acquire.gpu.global.u32 %0, [%1];" : "=r"(v) : "l"(cp) : "memory");
            if ((int)(v - tgt) >= 0) break;
            __nanosleep(20);
        }
    }
    __syncthreads();
}
// publish: red.release orders all prior global writes at gpu scope
static __device__ __forceinline__ void arrive_cnt(unsigned* cp) {
    __syncthreads();
    if (threadIdx.x == 0)
        asm volatile("red.release.gpu.global.add.u32 [%0], 1;" :: "l"(cp) : "memory");
}

// --- pipelined matmul slice: acc[p] += sum_k h[k][lane] * w[k][p] -----------
// wv: smem weight rows for this slice (4 x ulonglong2 per k, pre-offset)
// src: first h element for this lane (stride 32 floats per k), in L2
// Weights pipelined 3 deep in registers; h pipelined 16 deep. Fully unrolled.
template <int LEN>
static __device__ __forceinline__ void mm_pipe(
    const ulonglong2* __restrict__ wv, const float* __restrict__ src,
    unsigned long long acc[8])
{
    float hv[16];
    #pragma unroll
    for (int i = 0; i < (LEN < 16 ? LEN : 16); i++) hv[i] = ldcg(src + i * 32);

    ulonglong2 wb[3][4];
    #pragma unroll
    for (int s = 0; s < 3; s++)
        #pragma unroll
        for (int i = 0; i < 4; i++) wb[s][i] = wv[s * 4 + i];

    #pragma unroll
    for (int kk = 0; kk < LEN; kk++) {
        const int sl = kk % 3;
        unsigned long long h2 = pkdup(hv[kk & 15]);
        if (kk + 16 < LEN) hv[kk & 15] = ldcg(src + (kk + 16) * 32);
        ulonglong2 wa = wb[sl][0];
        ulonglong2 wq = wb[sl][1];
        ulonglong2 wc = wb[sl][2];
        ulonglong2 wd = wb[sl][3];
        if (kk + 3 < LEN) {
            #pragma unroll
            for (int i = 0; i < 4; i++) wb[sl][i] = wv[(kk + 3) * 4 + i];
        }
        ffma2(acc[0], h2, wa.x);
        ffma2(acc[1], h2, wa.y);
        ffma2(acc[2], h2, wq.x);
        ffma2(acc[3], h2, wq.y);
        ffma2(acc[4], h2, wc.x);
        ffma2(acc[5], h2, wc.y);
        ffma2(acc[6], h2, wd.x);
        ffma2(acc[7], h2, wd.y);
    }
}

// --------------------------- persistent kernel -----------------------------
__global__ void __launch_bounds__(512, 1)
lstm_persist(const float* __restrict__ b0f, const float* __restrict__ b0i,
             const float* __restrict__ b0c, const float* __restrict__ b0o,
             const float* __restrict__ b1f, const float* __restrict__ b1i,
             const float* __restrict__ b1c, const float* __restrict__ b1o,
             float* __restrict__ out)
{
    extern __shared__ char smem[];
    const ulonglong2* w0 = (const ulonglong2*)(smem + SMEM_W0);
    const ulonglong2* w1 = (const ulonglong2*)(smem + SMEM_W1);
    float2*      red = (float2*)(smem + SMEM_RED);
    unsigned long long* redu = (unsigned long long*)red;

    const int tid  = threadIdx.x;
    const int lane = tid & 31;       // = batch index
    const int warp = tid >> 5;       // 0..15
    const int cta  = blockIdx.x;
    const int U     = (cta < 68) ? 4 : 3;                       // 68*4+80*3=512
    const int ubase = (cta < 68) ? 4 * cta : 272 + 3 * (cta - 68);

    // load this CTA's weight images into SMEM (once)
    {
        const char* s0 = (const char*)(g_w0 + (size_t)cta * 768 * 8);
        #pragma unroll
        for (int i = 0; i < 6; i++)
            cp16((char*)smem + SMEM_W0 + tid * 16 + i * 8192, s0 + tid * 16 + i * 8192);
        const char* s1 = (const char*)(g_w1 + (size_t)cta * 1024 * 8);
        #pragma unroll
        for (int i = 0; i < 8; i++)
            cp16((char*)smem + SMEM_W1 + tid * 16 + i * 8192, s1 + tid * 16 + i * 8192);
        asm volatile("cp.async.commit_group;" ::: "memory");
        asm volatile("cp.async.wait_group 0;" ::: "memory");
    }
    __syncthreads();

    // warps 0-3 finalize L0 unit j; warps 4-7 finalize L1 unit j; 8-15 compute
    const int j  = warp & 3;
    const int uu = ubase + (j < U ? j : 0);
    float Bf = 0.f, Bi = 0.f, Bc = 0.f, Bo = 0.f;
    if (warp < 4)        { Bf = b0f[uu]; Bi = b0i[uu]; Bc = b0c[uu]; Bo = b0o[uu]; }
    else if (warp < 8)   { Bf = b1f[uu]; Bi = b1i[uu]; Bc = b1c[uu]; Bo = b1o[uu]; }
    float cst = 0.0f;                       // cell state lives in a register
    unsigned tgt = 0;                       // = t * NCTA at loop top
    unsigned long long acc[8];

    for (int t = 0; t < 1024; t++) {
        const int par = t & 1, par2 = par ^ 1;

        // ================= L0(t): gates0 = W0 . [x(t); h0(t-1)] ============
        #pragma unroll
        for (int p = 0; p < 8; p++) acc[p] = 0ULL;
        // x part: k in [warp*16, warp*16+16), no cross-CTA dependence
        mm_pipe<16>(w0 + (size_t)(warp * 16) * 4,
                    g_xT + (size_t)t * 8192 + (warp * 16) * 32 + lane, acc);
        // h0(t-1): published with cnt0 == t*NCTA
        wait_cnt(&g_cnt[0], tgt);
        mm_pipe<32>(w0 + (size_t)(256 + warp * 32) * 4,
                    &g_h[0][par2][warp * 32][0] + lane, acc);

        #pragma unroll
        for (int p = 0; p < 8; p++) redu[(warp * 8 + p) * 32 + lane] = acc[p];
        __syncthreads();
        if (warp < 4) {
            float2 sfi = make_float2(0.f, 0.f), sco = make_float2(0.f, 0.f);
            #pragma unroll
            for (int w = 0; w < 16; w++) {
                float2 a = red[(w * 8 + 2 * j) * 32 + lane];
                float2 b = red[(w * 8 + 2 * j + 1) * 32 + lane];
                sfi.x += a.x; sfi.y += a.y; sco.x += b.x; sco.y += b.y;
            }
            float f  = sigm(sfi.x + Bf);
            float ig = sigm(sfi.y + Bi);
            float gg = tanh_f(sco.x + Bc);
            float o  = sigm(sco.y + Bo);
            cst = f * cst + ig * gg;
            float h = o * tanh_f(cst);
            if (j < U) g_h[0][par][ubase + j][lane] = h;
        }
        arrive_cnt(&g_cnt[0]);   // cnt0 -> (t+1)*NCTA

        // ================= L1(t): gates1 = W1 . [h0(t); h1(t-1)] ===========
        #pragma unroll
        for (int p = 0; p < 8; p++) acc[p] = 0ULL;
        // h1(t-1): published with cnt1 == t*NCTA (slack: all of L0(t))
        wait_cnt(&g_cnt[1], tgt);
        mm_pipe<32>(w1 + (size_t)(512 + warp * 32) * 4,
                    &g_h[1][par2][warp * 32][0] + lane, acc);
        // h0(t): published just above; slack = h1-old half
        wait_cnt(&g_cnt[0], tgt + NCTA);
        mm_pipe<32>(w1 + (size_t)(warp * 32) * 4,
                    &g_h[0][par][warp * 32][0] + lane, acc);

        #pragma unroll
        for (int p = 0; p < 8; p++) redu[(warp * 8 + p) * 32 + lane] = acc[p];
        __syncthreads();
        if (warp >= 4 && warp < 8) {
            float2 sfi = make_float2(0.f, 0.f), sco = make_float2(0.f, 0.f);
            #pragma unroll
            for (int w = 0; w < 16; w++) {
                float2 a = red[(w * 8 + 2 * j) * 32 + lane];
                float2 b = red[(w * 8 + 2 * j + 1) * 32 + lane];
                sfi.x += a.x; sfi.y += a.y; sco.x += b.x; sco.y += b.y;
            }
            float f  = sigm(sfi.x + Bf);
            float ig = sigm(sfi.y + Bi);
            float gg = tanh_f(sco.x + Bc);
            float o  = sigm(sco.y + Bo);
            cst = f * cst + ig * gg;
            float h = o * tanh_f(cst);
            if (j < U) {
                int u = ubase + j;
                g_h[1][par][u][lane] = h;
                out[(size_t)lane * 524288 + (size_t)t * 512 + u] = h;
            }
        }
        arrive_cnt(&g_cnt[1]);   // cnt1 -> (t+1)*NCTA

        tgt += NCTA;
    }
}

// ------------------------------ fused prep ---------------------------------
// segments: [0, 8388608) transpose x | [.., +65536) zero g_h (+counters)
//           [.., +909312) w0 image   | [.., +1212416) w1 image
__global__ void prep_all(const float* __restrict__ x,
                         const float* __restrict__ W0f, const float* __restrict__ W0i,
                         const float* __restrict__ W0c, const float* __restrict__ W0o,
                         const float* __restrict__ W1f, const float* __restrict__ W1i,
                         const float* __restrict__ W1c, const float* __restrict__ W1o)
{
    long idx = (long)blockIdx.x * blockDim.x + threadIdx.x;
    if (idx < 8388608L) {                                   // x transpose
        int b = (int)(idx & 31);
        int c = (int)((idx >> 5) & 255);
        int t = (int)(idx >> 13);
        g_xT[idx] = x[(size_t)b * 262144 + (size_t)t * 256 + c];
        return;
    }
    idx -= 8388608L;
    if (idx < 65536L) {                                     // zero h state + counters
        if (idx < 2) g_cnt[idx] = 0u;
        (&g_h[0][0][0][0])[idx] = 0.f;
        return;
    }
    idx -= 65536L;
    int layer; long widx; int K;
    const float *Wf, *Wi, *Wc, *Wo;
    if (idx < (long)NCTA * 768 * 8) {
        layer = 0; widx = idx; K = 768; Wf = W0f; Wi = W0i; Wc = W0c; Wo = W0o;
    } else {
        layer = 1; widx = idx - (long)NCTA * 768 * 8; K = 1024;
        Wf = W1f; Wi = W1i; Wc = W1c; Wo = W1o;
        if (widx >= (long)NCTA * 1024 * 8) return;
    }
    int  p   = (int)(widx & 7);
    long r   = widx >> 3;
    int  k   = (int)(r % K);
    int  cta = (int)(r / K);
    int  Uc    = (cta < 68) ? 4 : 3;
    int  ubase = (cta < 68) ? 4 * cta : 272 + 3 * (cta - 68);
    int  jj = p >> 1, q = p & 1;
    float2 v = make_float2(0.f, 0.f);
    if (jj < Uc) {
        size_t o = (size_t)(ubase + jj) * K + k;
        v = q ? make_float2(Wc[o], Wo[o]) : make_float2(Wf[o], Wi[o]);
    }
    if (layer) g_w1[widx] = v; else g_w0[widx] = v;
}

// ------------------------------- launcher ----------------------------------
extern "C" void kernel_launch(void* const* d_in, const int* in_sizes, int n_in,
                              void* d_out, int out_size)
{
    const float* x   = (const float*)d_in[0];
    const float* W0f = (const float*)d_in[1];
    const float* b0f = (const float*)d_in[2];
    const float* W0i = (const float*)d_in[3];
    const float* b0i = (const float*)d_in[4];
    const float* W0c = (const float*)d_in[5];
    const float* b0c = (const float*)d_in[6];
    const float* W0o = (const float*)d_in[7];
    const float* b0o = (const float*)d_in[8];
    const float* W1f = (const float*)d_in[9];
    const float* b1f = (const float*)d_in[10];
    const float* W1i = (const float*)d_in[11];
    const float* b1i = (const float*)d_in[12];
    const float* W1c = (const float*)d_in[13];
    const float* b1c = (const float*)d_in[14];
    const float* W1o = (const float*)d_in[15];
    const float* b1o = (const float*)d_in[16];
    float* out = (float*)d_out;

    cudaFuncSetAttribute(lstm_persist,
                         cudaFuncAttributeMaxDynamicSharedMemorySize, SMEM_TOTAL);

    // total prep items = 8388608 + 65536 + 909312 + 1212416 = 10575872 = 41312*256
    prep_all<<<41312, 256>>>(x, W0f, W0i, W0c, W0o, W1f, W1i, W1c, W1o);
    lstm_persist<<<NCTA, 512, SMEM_TOTAL>>>(b0f, b0i, b0c, b0o,
                                            b1f, b1i, b1c, b1o, out);
}

// round 15
// speedup vs baseline: 1.4182x; 1.0058x over previous
#include <cuda_runtime.h>
#include <cstdint>

// ============================================================================
// Persistent 2-layer LSTM for GB300 (sm_103a) — R9.
//   R6 topology: 148 CTAs x 512 thr (16 warps), per-CTA smem weight images,
//   lane = batch, split-counter grid sync.
//   NEW: fully-unrolled inner loops with explicit register pipelines —
//   weights 3 k-iters deep (LDS lat 29cy covered), h 16 deep (L2 lat covered),
//   no per-iteration guards (they caused R8's ALU blowup).
// ============================================================================

#define NCTA 148
#define SMEM_W0   0                 // [768][8] float2  = 49152 B
#define SMEM_W1   49152             // [1024][8] float2 = 65536 B
#define SMEM_RED  114688            // 16 warps x 8 pairs x 32 lanes x 8B = 32768 B
#define SMEM_TOTAL 147456           // 144 KB

// ------------------------- device-global scratch ---------------------------
__device__ float g_xT[1024 * 256 * 32];            // x transposed: [t][c][b]
__device__ float g_h[2][2][512][32];               // [layer][parity][unit][batch]
__device__ float2 g_w0[(size_t)NCTA * 768 * 8];    // per-CTA weight images, layer0
__device__ float2 g_w1[(size_t)NCTA * 1024 * 8];   // per-CTA weight images, layer1
__device__ unsigned g_cnt[2];                      // split barrier counters

// ------------------------------ helpers ------------------------------------
static __device__ __forceinline__ void cp16(void* d, const void* s) {
    unsigned ds = (unsigned)__cvta_generic_to_shared(d);
    asm volatile("cp.async.cg.shared.global [%0], [%1], 16;" :: "r"(ds), "l"(s));
}
static __device__ __forceinline__ float sigm(float x) {
    return 1.0f / (1.0f + __expf(-x));
}
static __device__ __forceinline__ float tanh_f(float x) {
    return 1.0f - 2.0f / (__expf(2.0f * x) + 1.0f);
}
static __device__ __forceinline__ unsigned long long pkdup(float v) {
    unsigned u = __float_as_uint(v);
    unsigned long long r;
    asm("mov.b64 %0, {%1, %1};" : "=l"(r) : "r"(u));
    return r;
}
static __device__ __forceinline__ void ffma2(unsigned long long& acc,
                                             unsigned long long a,
                                             unsigned long long b) {
    asm("fma.rn.f32x2 %0, %1, %2, %0;" : "+l"(acc) : "l"(a), "l"(b));
}
static __device__ __forceinline__ float ldcg(const float* p) {
    float v;
    asm volatile("ld.global.cg.f32 %0, [%1];" : "=f"(v) : "l"(p));
    return v;
}

// spin until *cp >= tgt (tid0 spins, CTA released together)
static __device__ __forceinline__ void wait_cnt(unsigned* cp, unsigned tgt) {
    if (threadIdx.x == 0) {
        unsigned v;
        for (;;) {
            asm volatile("ld.acquire.gpu.global.u32 %0, [%1];" : "=r"(v) : "l"(cp) : "memory");
            if ((int)(v - tgt) >= 0) break;
            __nanosleep(20);
        }
    }
    __syncthreads();
}
// publish: red.release orders all prior global writes at gpu scope
static __device__ __forceinline__ void arrive_cnt(unsigned* cp) {
    __syncthreads();
    if (threadIdx.x == 0)
        asm volatile("red.release.gpu.global.add.u32 [%0], 1;" :: "l"(cp) : "memory");
}

// --- pipelined matmul slice: acc[p] += sum_k h[k][lane] * w[k][p] -----------
// wv: smem weight rows for this slice (4 x ulonglong2 per k, pre-offset)
// src: first h element for this lane (stride 32 floats per k), in L2
// Weights pipelined 3 deep in registers; h pipelined 16 deep. Fully unrolled.
template <int LEN>
static __device__ __forceinline__ void mm_pipe(
    const ulonglong2* __restrict__ wv, const float* __restrict__ src,
    unsigned long long acc[8])
{
    float hv[16];
    #pragma unroll
    for (int i = 0; i < (LEN < 16 ? LEN : 16); i++) hv[i] = ldcg(src + i * 32);

    ulonglong2 wb[3][4];
    #pragma unroll
    for (int s = 0; s < 3; s++)
        #pragma unroll
        for (int i = 0; i < 4; i++) wb[s][i] = wv[s * 4 + i];

    #pragma unroll
    for (int kk = 0; kk < LEN; kk++) {
        const int sl = kk % 3;
        unsigned long long h2 = pkdup(hv[kk & 15]);
        if (kk + 16 < LEN) hv[kk & 15] = ldcg(src + (kk + 16) * 32);
        ulonglong2 wa = wb[sl][0];
        ulonglong2 wq = wb[sl][1];
        ulonglong2 wc = wb[sl][2];
        ulonglong2 wd = wb[sl][3];
        if (kk + 3 < LEN) {
            #pragma unroll
            for (int i = 0; i < 4; i++) wb[sl][i] = wv[(kk + 3) * 4 + i];
        }
        ffma2(acc[0], h2, wa.x);
        ffma2(acc[1], h2, wa.y);
        ffma2(acc[2], h2, wq.x);
        ffma2(acc[3], h2, wq.y);
        ffma2(acc[4], h2, wc.x);
        ffma2(acc[5], h2, wc.y);
        ffma2(acc[6], h2, wd.x);
        ffma2(acc[7], h2, wd.y);
    }
}

// --------------------------- persistent kernel -----------------------------
__global__ void __launch_bounds__(512, 1)
lstm_persist(const float* __restrict__ b0f, const float* __restrict__ b0i,
             const float* __restrict__ b0c, const float* __restrict__ b0o,
             const float* __restrict__ b1f, const float* __restrict__ b1i,
             const float* __restrict__ b1c, const float* __restrict__ b1o,
             float* __restrict__ out)
{
    extern __shared__ char smem[];
    const ulonglong2* w0 = (const ulonglong2*)(smem + SMEM_W0);
    const ulonglong2* w1 = (const ulonglong2*)(smem + SMEM_W1);
    float2*      red = (float2*)(smem + SMEM_RED);
    unsigned long long* redu = (unsigned long long*)red;

    const int tid  = threadIdx.x;
    const int lane = tid & 31;       // = batch index
    const int warp = tid >> 5;       // 0..15
    const int cta  = blockIdx.x;
    const int U     = (cta < 68) ? 4 : 3;                       // 68*4+80*3=512
    const int ubase = (cta < 68) ? 4 * cta : 272 + 3 * (cta - 68);

    // load this CTA's weight images into SMEM (once)
    {
        const char* s0 = (const char*)(g_w0 + (size_t)cta * 768 * 8);
        #pragma unroll
        for (int i = 0; i < 6; i++)
            cp16((char*)smem + SMEM_W0 + tid * 16 + i * 8192, s0 + tid * 16 + i * 8192);
        const char* s1 = (const char*)(g_w1 + (size_t)cta * 1024 * 8);
        #pragma unroll
        for (int i = 0; i < 8; i++)
            cp16((char*)smem + SMEM_W1 + tid * 16 + i * 8192, s1 + tid * 16 + i * 8192);
        asm volatile("cp.async.commit_group;" ::: "memory");
        asm volatile("cp.async.wait_group 0;" ::: "memory");
    }
    __syncthreads();

    // warps 0-3 finalize L0 unit j; warps 4-7 finalize L1 unit j; 8-15 compute
    const int j  = warp & 3;
    const int uu = ubase + (j < U ? j : 0);
    float Bf = 0.f, Bi = 0.f, Bc = 0.f, Bo = 0.f;
    if (warp < 4)        { Bf = b0f[uu]; Bi = b0i[uu]; Bc = b0c[uu]; Bo = b0o[uu]; }
    else if (warp < 8)   { Bf = b1f[uu]; Bi = b1i[uu]; Bc = b1c[uu]; Bo = b1o[uu]; }
    float cst = 0.0f;                       // cell state lives in a register
    unsigned tgt = 0;                       // = t * NCTA at loop top
    unsigned long long acc[8];

    for (int t = 0; t < 1024; t++) {
        const int par = t & 1, par2 = par ^ 1;

        // ================= L0(t): gates0 = W0 . [x(t); h0(t-1)] ============
        #pragma unroll
        for (int p = 0; p < 8; p++) acc[p] = 0ULL;
        // x part: k in [warp*16, warp*16+16), no cross-CTA dependence
        mm_pipe<16>(w0 + (size_t)(warp * 16) * 4,
                    g_xT + (size_t)t * 8192 + (warp * 16) * 32 + lane, acc);
        // h0(t-1): published with cnt0 == t*NCTA
        wait_cnt(&g_cnt[0], tgt);
        mm_pipe<32>(w0 + (size_t)(256 + warp * 32) * 4,
                    &g_h[0][par2][warp * 32][0] + lane, acc);

        #pragma unroll
        for (int p = 0; p < 8; p++) redu[(warp * 8 + p) * 32 + lane] = acc[p];
        __syncthreads();
        if (warp < 4) {
            float2 sfi = make_float2(0.f, 0.f), sco = make_float2(0.f, 0.f);
            #pragma unroll
            for (int w = 0; w < 16; w++) {
                float2 a = red[(w * 8 + 2 * j) * 32 + lane];
                float2 b = red[(w * 8 + 2 * j + 1) * 32 + lane];
                sfi.x += a.x; sfi.y += a.y; sco.x += b.x; sco.y += b.y;
            }
            float f  = sigm(sfi.x + Bf);
            float ig = sigm(sfi.y + Bi);
            float gg = tanh_f(sco.x + Bc);
            float o  = sigm(sco.y + Bo);
            cst = f * cst + ig * gg;
            float h = o * tanh_f(cst);
            if (j < U) g_h[0][par][ubase + j][lane] = h;
        }
        arrive_cnt(&g_cnt[0]);   // cnt0 -> (t+1)*NCTA

        // ================= L1(t): gates1 = W1 . [h0(t); h1(t-1)] ===========
        #pragma unroll
        for (int p = 0; p < 8; p++) acc[p] = 0ULL;
        // h1(t-1): published with cnt1 == t*NCTA (slack: all of L0(t))
        wait_cnt(&g_cnt[1], tgt);
        mm_pipe<32>(w1 + (size_t)(512 + warp * 32) * 4,
                    &g_h[1][par2][warp * 32][0] + lane, acc);
        // h0(t): published just above; slack = h1-old half
        wait_cnt(&g_cnt[0], tgt + NCTA);
        mm_pipe<32>(w1 + (size_t)(warp * 32) * 4,
                    &g_h[0][par][warp * 32][0] + lane, acc);

        #pragma unroll
        for (int p = 0; p < 8; p++) redu[(warp * 8 + p) * 32 + lane] = acc[p];
        __syncthreads();
        if (warp >= 4 && warp < 8) {
            float2 sfi = make_float2(0.f, 0.f), sco = make_float2(0.f, 0.f);
            #pragma unroll
            for (int w = 0; w < 16; w++) {
                float2 a = red[(w * 8 + 2 * j) * 32 + lane];
                float2 b = red[(w * 8 + 2 * j + 1) * 32 + lane];
                sfi.x += a.x; sfi.y += a.y; sco.x += b.x; sco.y += b.y;
            }
            float f  = sigm(sfi.x + Bf);
            float ig = sigm(sfi.y + Bi);
            float gg = tanh_f(sco.x + Bc);
            float o  = sigm(sco.y + Bo);
            cst = f * cst + ig * gg;
            float h = o * tanh_f(cst);
            if (j < U) {
                int u = ubase + j;
                g_h[1][par][u][lane] = h;
                out[(size_t)lane * 524288 + (size_t)t * 512 + u] = h;
            }
        }
        arrive_cnt(&g_cnt[1]);   // cnt1 -> (t+1)*NCTA

        tgt += NCTA;
    }
}

// ------------------------------ fused prep ---------------------------------
// segments: [0, 8388608) transpose x | [.., +65536) zero g_h (+counters)
//           [.., +909312) w0 image   | [.., +1212416) w1 image
__global__ void prep_all(const float* __restrict__ x,
                         const float* __restrict__ W0f, const float* __restrict__ W0i,
                         const float* __restrict__ W0c, const float* __restrict__ W0o,
                         const float* __restrict__ W1f, const float* __restrict__ W1i,
                         const float* __restrict__ W1c, const float* __restrict__ W1o)
{
    long idx = (long)blockIdx.x * blockDim.x + threadIdx.x;
    if (idx < 8388608L) {                                   // x transpose
        int b = (int)(idx & 31);
        int c = (int)((idx >> 5) & 255);
        int t = (int)(idx >> 13);
        g_xT[idx] = x[(size_t)b * 262144 + (size_t)t * 256 + c];
        return;
    }
    idx -= 8388608L;
    if (idx < 65536L) {                                     // zero h state + counters
        if (idx < 2) g_cnt[idx] = 0u;
        (&g_h[0][0][0][0])[idx] = 0.f;
        return;
    }
    idx -= 65536L;
    int layer; long widx; int K;
    const float *Wf, *Wi, *Wc, *Wo;
    if (idx < (long)NCTA * 768 * 8) {
        layer = 0; widx = idx; K = 768; Wf = W0f; Wi = W0i; Wc = W0c; Wo = W0o;
    } else {
        layer = 1; widx = idx - (long)NCTA * 768 * 8; K = 1024;
        Wf = W1f; Wi = W1i; Wc = W1c; Wo = W1o;
        if (widx >= (long)NCTA * 1024 * 8) return;
    }
    int  p   = (int)(widx & 7);
    long r   = widx >> 3;
    int  k   = (int)(r % K);
    int  cta = (int)(r / K);
    int  Uc    = (cta < 68) ? 4 : 3;
    int  ubase = (cta < 68) ? 4 * cta : 272 + 3 * (cta - 68);
    int  jj = p >> 1, q = p & 1;
    float2 v = make_float2(0.f, 0.f);
    if (jj < Uc) {
        size_t o = (size_t)(ubase + jj) * K + k;
        v = q ? make_float2(Wc[o], Wo[o]) : make_float2(Wf[o], Wi[o]);
    }
    if (layer) g_w1[widx] = v; else g_w0[widx] = v;
}

// ------------------------------- launcher ----------------------------------
extern "C" void kernel_launch(void* const* d_in, const int* in_sizes, int n_in,
                              void* d_out, int out_size)
{
    const float* x   = (const float*)d_in[0];
    const float* W0f = (const float*)d_in[1];
    const float* b0f = (const float*)d_in[2];
    const float* W0i = (const float*)d_in[3];
    const float* b0i = (const float*)d_in[4];
    const float* W0c = (const float*)d_in[5];
    const float* b0c = (const float*)d_in[6];
    const float* W0o = (const float*)d_in[7];
    const float* b0o = (const float*)d_in[8];
    const float* W1f = (const float*)d_in[9];
    const float* b1f = (const float*)d_in[10];
    const float* W1i = (const float*)d_in[11];
    const float* b1i = (const float*)d_in[12];
    const float* W1c = (const float*)d_in[13];
    const float* b1c = (const float*)d_in[14];
    const float* W1o = (const float*)d_in[15];
    const float* b1o = (const float*)d_in[16];
    float* out = (float*)d_out;

    cudaFuncSetAttribute(lstm_persist,
                         cudaFuncAttributeMaxDynamicSharedMemorySize, SMEM_TOTAL);

    // total prep items = 8388608 + 65536 + 909312 + 1212416 = 10575872 = 41312*256
    prep_all<<<41312, 256>>>(x, W0f, W0i, W0c, W0o, W1f, W1i, W1c, W1o);
    lstm_persist<<<NCTA, 512, SMEM_TOTAL>>>(b0f, b0i, b0c, b0o,
                                            b1f, b1i, b1c, b1o, out);
}